// round 13
// baseline (speedup 1.0000x reference)
#include <cuda_runtime.h>
#include <cuda_bf16.h>
#include <math.h>
#include <stdint.h>

// Problem shape (fixed)
#define D_DIM 1024
#define C_NUM 256
#define S_SZ  16384
#define Q_SZ  4096

// HMMA tile config — single bf16 pass
#define BM 128
#define BN 128
#define BK 32
#define NKITER (D_DIM / BK)        // 32
#define NSTAGE 5
#define APITCH 80                  // padded row pitch bytes (64B data); aggregate-conflict-free
#define MAT_BYTES (128 * APITCH)   // 10240
#define STAGE_BYTES (2 * MAT_BYTES)// A,B = 20480
#define SIMS_PITCH 132             // floats; multiple of 4 -> float4 aligned
#define SMEM_BYTES (NSTAGE * STAGE_BYTES)   // 102400 (sims 128*132*4=67584 overlays)

// persistent scheduling: unit = one (qtile, stile)
#define NQT (Q_SZ / BM)            // 32
#define NST (S_SZ / BN)            // 128
#define NUNITS (NQT * NST)         // 4096
#define NWORKERS 296               // 2 per SM

#define NROWS_PB 16                // rows per block in k_norm_sup

// ---------------- device scratch ----------------------------------------------
__device__ __align__(256) __nv_bfloat16 g_supNB[(size_t)S_SZ * D_DIM]; // l2-normalized (orig order)
__device__ __align__(256) __nv_bfloat16 g_supB[(size_t)S_SZ * D_DIM];  // centered, sorted
__device__ __align__(256) __nv_bfloat16 g_qryB[(size_t)Q_SZ * D_DIM];
__device__ float g_colsum8[8 * D_DIM];
__device__ int   g_counts[C_NUM];
__device__ float g_mu[D_DIM];
__device__ int   g_offsets[C_NUM];
__device__ int   g_cursor[C_NUM];
__device__ float g_logcounts[C_NUM];
__device__ int   g_slab[S_SZ];
__device__ int   g_srcidx[S_SZ];
__device__ float g_bins[(size_t)Q_SZ * C_NUM];
__device__ unsigned g_tilectr;

// ---------------- asm helpers ---------------------------------------------------
__device__ __forceinline__ uint32_t smem_u32(const void* p) {
    uint32_t a;
    asm("{ .reg .u64 t; cvta.to.shared.u64 t, %1; cvt.u32.u64 %0, t; }" : "=r"(a) : "l"(p));
    return a;
}
#define CP16(sa, g) \
    asm volatile("cp.async.cg.shared.global [%0], [%1], 16;" :: "r"(sa), "l"(g))
#define CP_COMMIT() asm volatile("cp.async.commit_group;" ::: "memory")
#define CP_WAIT3()  asm volatile("cp.async.wait_group 3;" ::: "memory")
#define CP_WAIT0()  asm volatile("cp.async.wait_group 0;" ::: "memory")
#define LDSM_X4(r0, r1, r2, r3, addr) \
    asm volatile("ldmatrix.sync.aligned.m8n8.x4.shared.b16 {%0,%1,%2,%3}, [%4];" \
                 : "=r"(r0), "=r"(r1), "=r"(r2), "=r"(r3) : "r"(addr))
#define MMA16816(d, a, b) \
    asm volatile("mma.sync.aligned.m16n8k16.row.col.f32.bf16.bf16.f32 " \
                 "{%0,%1,%2,%3}, {%4,%5,%6,%7}, {%8,%9}, {%0,%1,%2,%3};" \
                 : "+f"((d)[0]), "+f"((d)[1]), "+f"((d)[2]), "+f"((d)[3]) \
                 : "r"((a)[0]), "r"((a)[1]), "r"((a)[2]), "r"((a)[3]), \
                   "r"((b)[0]), "r"((b)[1]))

// 2^t via degree-6 poly on [-0.5,0.5] + exponent splice. rel err ~1e-8.
__device__ __forceinline__ float fast_exp2(float tt) {
    float n = rintf(tt);
    float f = tt - n;
    float p = 1.5403530394e-4f;
    p = fmaf(p, f, 1.3333558146e-3f);
    p = fmaf(p, f, 9.6181291076e-3f);
    p = fmaf(p, f, 5.5504108664e-2f);
    p = fmaf(p, f, 2.4022650696e-1f);
    p = fmaf(p, f, 6.9314718056e-1f);
    p = fmaf(p, f, 1.0f);
    int ni = (int)n;
    return p * __int_as_float((ni + 127) << 23);
}

// log2 via exponent split + atanh-form poly. abs err ~2e-5 over [1,2).
__device__ __forceinline__ float fast_log2(float x) {
    int bits = __float_as_int(x);
    int e = ((bits >> 23) & 255) - 127;
    float m = __int_as_float((bits & 0x007FFFFF) | 0x3F800000);  // [1,2)
    float tq = (m - 1.0f) / (m + 1.0f);
    float t2 = tq * tq;
    float p = 0.4121985831f;            // 2/(7 ln2)
    p = fmaf(p, t2, 0.5770780163f);     // 2/(5 ln2)
    p = fmaf(p, t2, 0.9617966939f);     // 2/(3 ln2)
    p = fmaf(p, t2, 2.8853900818f);     // 2/ln2
    return (float)e + p * tq;
}

// ---------------- block reductions (256 threads) -------------------------------
__device__ __forceinline__ float brsum256(float v, float* sm) {
#pragma unroll
    for (int o = 16; o > 0; o >>= 1) v += __shfl_xor_sync(0xffffffffu, v, o);
    __syncthreads();
    if ((threadIdx.x & 31) == 0) sm[threadIdx.x >> 5] = v;
    __syncthreads();
    float s = sm[0];
#pragma unroll
    for (int i = 1; i < 8; i++) s += sm[i];
    return s;
}
__device__ __forceinline__ float brmax256(float v, float* sm) {
#pragma unroll
    for (int o = 16; o > 0; o >>= 1) v = fmaxf(v, __shfl_xor_sync(0xffffffffu, v, o));
    __syncthreads();
    if ((threadIdx.x & 31) == 0) sm[threadIdx.x >> 5] = v;
    __syncthreads();
    float s = sm[0];
#pragma unroll
    for (int i = 1; i < 8; i++) s = fmaxf(s, sm[i]);
    return s;
}

__device__ __forceinline__ void bf16_store(__nv_bfloat16* dst, size_t row, int t, float4 v) {
    __nv_bfloat162 p0(__float2bfloat16(v.x), __float2bfloat16(v.y));
    __nv_bfloat162 p1(__float2bfloat16(v.z), __float2bfloat16(v.w));
    uint2 pv;
    pv.x = *(uint32_t*)&p0; pv.y = *(uint32_t*)&p1;
    ((uint2*)(dst + row * D_DIM))[t] = pv;
}
__device__ __forceinline__ float4 bf16_load4(const __nv_bfloat16* src, size_t row, int t) {
    uint2 pv = ((const uint2*)(src + row * D_DIM))[t];
    __nv_bfloat162 p0 = *(__nv_bfloat162*)&pv.x;
    __nv_bfloat162 p1 = *(__nv_bfloat162*)&pv.y;
    float4 v;
    v.x = __bfloat162float(p0.x); v.y = __bfloat162float(p0.y);
    v.z = __bfloat162float(p1.x); v.w = __bfloat162float(p1.y);
    return v;
}

// ---------------- prep kernels --------------------------------------------------
__global__ void k_init() {
    int i = blockIdx.x * blockDim.x + threadIdx.x;
    int stride = gridDim.x * blockDim.x;
    for (int j = i; j < Q_SZ * C_NUM; j += stride) g_bins[j] = 0.f;
    if (i < 8 * D_DIM) g_colsum8[i] = 0.f;
    if (i < C_NUM) { g_counts[i] = 0; g_cursor[i] = 0; }
    if (i == 0) g_tilectr = 0u;
}

// l2-normalize 16 rows/block (store bf16) + block-local colsum + label histogram,
// then one flush: 1024 colsum atomics + <=256 count atomics per block.
__global__ void k_norm_sup(const float* __restrict__ sup, const int* __restrict__ labels) {
    __shared__ float sm[8];
    __shared__ float cs[D_DIM];
    __shared__ int hist[C_NUM];
    int t = threadIdx.x;
#pragma unroll
    for (int j = 0; j < 4; j++) cs[t + j * 256] = 0.f;
    hist[t] = 0;
    __syncthreads();

    int r0 = blockIdx.x * NROWS_PB;
    for (int i = 0; i < NROWS_PB; i++) {
        int r = r0 + i;
        float4 v = ((const float4*)(sup + (size_t)r * D_DIM))[t];
        float ss = v.x * v.x + v.y * v.y + v.z * v.z + v.w * v.w;
        ss = brsum256(ss, sm);
        float inv = 1.f / fmaxf(sqrtf(ss), 1e-8f);
        v.x *= inv; v.y *= inv; v.z *= inv; v.w *= inv;
        bf16_store(g_supNB, (size_t)r, t, v);
        // thread t owns columns 4t..4t+3 -> no race
        cs[t * 4 + 0] += v.x;
        cs[t * 4 + 1] += v.y;
        cs[t * 4 + 2] += v.z;
        cs[t * 4 + 3] += v.w;
        if (t == 0) atomicAdd(&hist[labels[r]], 1);
    }
    __syncthreads();
    float* g = g_colsum8 + (blockIdx.x & 7) * D_DIM;
#pragma unroll
    for (int j = 0; j < 4; j++) atomicAdd(&g[t + j * 256], cs[t + j * 256]);
    if (hist[t]) atomicAdd(&g_counts[t], hist[t]);
}

// mu + parallel exclusive scan + logcounts (single block, 1024 threads)
__global__ void k_mu_scan() {
    __shared__ int sc_sm[C_NUM];
    int t = threadIdx.x;
    if (t < D_DIM) {
        float s = 0.f;
#pragma unroll
        for (int r = 0; r < 8; r++) s += g_colsum8[r * D_DIM + t];
        g_mu[t] = s / (float)S_SZ;
    }
    int cnt = 0;
    if (t < C_NUM) { cnt = g_counts[t]; sc_sm[t] = cnt; }
    __syncthreads();
#pragma unroll
    for (int off = 1; off < C_NUM; off <<= 1) {
        int v = 0;
        if (t < C_NUM && t >= off) v = sc_sm[t - off];
        __syncthreads();
        if (t < C_NUM) sc_sm[t] += v;
        __syncthreads();
    }
    if (t < C_NUM) {
        g_offsets[t] = sc_sm[t] - cnt;   // exclusive
        g_logcounts[t] = logf(fmaxf((float)cnt, 1.f));
    }
}

__global__ void k_scatter(const int* __restrict__ labels) {
    int s = blockIdx.x * blockDim.x + threadIdx.x;
    if (s < S_SZ) {
        int lb = labels[s];
        int pos = g_offsets[lb] + atomicAdd(&g_cursor[lb], 1);
        g_srcidx[pos] = s;
        g_slab[pos] = lb;
    }
}

// fused center(support, sorted order) + query transform — one row per block
// (per-row blocks hide the reduce/rsqrt latency chain best; R11 chunking regressed)
__global__ void k_centerquery(const float* __restrict__ qry) {
    __shared__ float sm[8];
    int b = blockIdx.x, t = threadIdx.x;
    if (b < S_SZ) {
        int src = g_srcidx[b];
        float4 v = bf16_load4(g_supNB, (size_t)src, t);
        float4 m = ((const float4*)g_mu)[t];
        v.x -= m.x; v.y -= m.y; v.z -= m.z; v.w -= m.w;
        float ss = v.x * v.x + v.y * v.y + v.z * v.z + v.w * v.w;
        ss = brsum256(ss, sm);
        float inv = 1.f / fmaxf(sqrtf(ss), 1e-8f);
        v.x *= inv; v.y *= inv; v.z *= inv; v.w *= inv;
        bf16_store(g_supB, (size_t)b, t, v);
    } else {
        int r = b - S_SZ;
        float4 v = ((const float4*)(qry + (size_t)r * D_DIM))[t];
        float ss = v.x * v.x + v.y * v.y + v.z * v.z + v.w * v.w;
        ss = brsum256(ss, sm);
        float inv = 1.f / fmaxf(sqrtf(ss), 1e-8f);
        v.x *= inv; v.y *= inv; v.z *= inv; v.w *= inv;
        float4 m = ((const float4*)g_mu)[t];
        v.x -= m.x; v.y -= m.y; v.z -= m.z; v.w -= m.w;
        float ss2 = v.x * v.x + v.y * v.y + v.z * v.z + v.w * v.w;
        ss2 = brsum256(ss2, sm);
        float inv2 = 1.f / fmaxf(sqrtf(ss2), 1e-8f);
        v.x *= inv2; v.y *= inv2; v.z *= inv2; v.w *= inv2;
        bf16_store(g_qryB, (size_t)r, t, v);
    }
}

// ---------------- fused persistent HMMA GEMM + exp + segment binning -----------
// Pipeline: 5 stages, single-kt commit groups, wait_group 3, issue kt+4 while
// reading kt. Write target (kt+4)%5 aliases read stage (kt-1)%5 — protected by
// the per-iteration __syncthreads after the wait (same relation as the proven
// 4-stage design; only in-flight depth grows 2->3).
__global__ __launch_bounds__(256, 2)
void k_attn(const float* __restrict__ ls_ptr) {
    extern __shared__ __align__(16) char dsm[];
    __shared__ int slab_sm[128];
    __shared__ unsigned unit_sm;
    uint32_t smem_base = smem_u32(dsm);
    float* sims = (float*)dsm;   // overlay on stage buffers during epilogue

    int t = threadIdx.x;
    int wid = t >> 5, lane = t & 31;
    int wm = wid & 1, wn = wid >> 1;

    float sc = fminf(fmaxf(*ls_ptr, 1.f), 20.f);
    float scl2 = sc * 1.4426950408889634f;  // fold scale into log2(e)

    if (t == 0) unit_sm = atomicAdd(&g_tilectr, 1u);
    __syncthreads();
    unsigned u = unit_sm;

    while (u < NUNITS) {
        int q0 = (int)(u >> 7) * BM;
        int s0 = (int)(u & 127) * BN;
        if (t < BN) slab_sm[t] = g_slab[s0 + t];

        float acc[4][4][4];
#pragma unroll
        for (int mt = 0; mt < 4; mt++)
#pragma unroll
            for (int nt = 0; nt < 4; nt++)
#pragma unroll
                for (int e = 0; e < 4; e++) acc[mt][nt][e] = 0.f;

#define ISSUE(KT)                                                               \
        do {                                                                    \
            int kt_ = (KT);                                                     \
            if (kt_ < NKITER) {                                                 \
                int k0_ = kt_ * BK;                                             \
                uint32_t sb_ = smem_base + (kt_ % NSTAGE) * STAGE_BYTES;        \
                _Pragma("unroll")                                               \
                for (int m_ = 0; m_ < 2; m_++) {                                \
                    const __nv_bfloat16* base_ = (m_ == 0) ? g_qryB : g_supB;   \
                    int rb_ = (m_ == 0) ? q0 : s0;                              \
                    _Pragma("unroll")                                           \
                    for (int rc_ = 0; rc_ < 2; rc_++) {                         \
                        int i_ = t + rc_ * 256;                                 \
                        int row_ = i_ >> 2, ch_ = i_ & 3;                       \
                        const void* g_ = base_ +                                \
                            (size_t)(rb_ + row_) * D_DIM + k0_ + ch_ * 8;       \
                        uint32_t sa_ = sb_ + m_ * MAT_BYTES +                   \
                            row_ * APITCH + ch_ * 16;                           \
                        CP16(sa_, g_);                                          \
                    }                                                           \
                }                                                               \
            }                                                                   \
            CP_COMMIT();                                                        \
        } while (0)

        ISSUE(0);
        ISSUE(1);
        ISSUE(2);
        ISSUE(3);

        for (int kt = 0; kt < NKITER; kt++) {
            CP_WAIT3();
            __syncthreads();
            ISSUE(kt + 4);

            uint32_t sb = smem_base + (kt % NSTAGE) * STAGE_BYTES;
#pragma unroll
            for (int ks = 0; ks < 2; ks++) {
                uint32_t koff = ks * 32 + ((lane >> 4) << 4);
                uint32_t ah[4][4], bh[4][2];
#pragma unroll
                for (int mt = 0; mt < 4; mt++) {
                    uint32_t ra = sb + (uint32_t)(wm * 64 + mt * 16 + (lane & 15)) * APITCH + koff;
                    LDSM_X4(ah[mt][0], ah[mt][1], ah[mt][2], ah[mt][3], ra);
                }
#pragma unroll
                for (int p = 0; p < 2; p++) {
                    uint32_t rb2 = sb + MAT_BYTES +
                        (uint32_t)(wn * 32 + p * 16 + (lane & 15)) * APITCH + koff;
                    uint32_t x0, x1, x2, x3;
                    LDSM_X4(x0, x1, x2, x3, rb2);
                    bh[2 * p][0] = x0; bh[2 * p + 1][0] = x1;
                    bh[2 * p][1] = x2; bh[2 * p + 1][1] = x3;
                }
#pragma unroll
                for (int mt = 0; mt < 4; mt++)
#pragma unroll
                    for (int nt = 0; nt < 4; nt++)
                        MMA16816(acc[mt][nt], ah[mt], bh[nt]);
            }
        }
#undef ISSUE

        // ---- epilogue: prefetch next unit, exp -> sims smem -> binning ----
        CP_WAIT0();
        if (t == 0) unit_sm = atomicAdd(&g_tilectr, 1u);   // hide atomic latency
        __syncthreads();   // stages free; overlay sims

#pragma unroll
        for (int mt = 0; mt < 4; mt++) {
            int q = wm * 64 + mt * 16 + (lane >> 2);
#pragma unroll
            for (int nt = 0; nt < 4; nt++) {
                int c = wn * 32 + nt * 8 + (lane & 3) * 2;
                float2 v0, v1;
                v0.x = fast_exp2(acc[mt][nt][0] * scl2);
                v0.y = fast_exp2(acc[mt][nt][1] * scl2);
                v1.x = fast_exp2(acc[mt][nt][2] * scl2);
                v1.y = fast_exp2(acc[mt][nt][3] * scl2);
                *(float2*)&sims[(size_t)q * SIMS_PITCH + c] = v0;
                *(float2*)&sims[(size_t)(q + 8) * SIMS_PITCH + c] = v1;
            }
        }
        __syncthreads();

        {
            int q = t >> 1, h = t & 1;
            int cb = h * 64;
            const float* srow = &sims[(size_t)q * SIMS_PITCH + cb];
            float run = 0.f;
            int cur = slab_sm[cb];
#pragma unroll
            for (int i4 = 0; i4 < 16; i4++) {
                float4 v4 = *(const float4*)(srow + i4 * 4);
#pragma unroll
                for (int j = 0; j < 4; j++) {
                    int i = i4 * 4 + j;
                    int lb = slab_sm[cb + i];
                    float v = (j == 0) ? v4.x : (j == 1) ? v4.y : (j == 2) ? v4.z : v4.w;
                    if (lb != cur) {
                        atomicAdd(&g_bins[(size_t)(q0 + q) * C_NUM + cur], run);
                        run = 0.f; cur = lb;
                    }
                    run += v;
                }
            }
            atomicAdd(&g_bins[(size_t)(q0 + q) * C_NUM + cur], run);
        }
        __syncthreads();   // sims/slab reads done before next tile reuses smem
        u = unit_sm;
    }
}

// ---------------- finalize (uniq folded in: block 0 writes unique_classes) ------
__global__ void k_final(const float* __restrict__ cp_ptr,
                        float* __restrict__ logits_out,
                        float* __restrict__ uniq_out,
                        float* __restrict__ conf_out) {
    __shared__ float sm[8];
    const float LN2 = 0.6931471805599453f;
    int q = blockIdx.x, c = threadIdx.x;
    if (q == 0 && uniq_out) uniq_out[c] = (float)c;
    float mass = g_bins[(size_t)q * C_NUM + c];
    float Z = brsum256(mass, sm);
    float ratio = fmaxf(mass / Z, 1e-8f);
    float lg = fast_log2(ratio) * LN2 + (*cp_ptr) * g_logcounts[c];
    logits_out[(size_t)q * C_NUM + c] = lg;
    if (conf_out) {
        float m = brmax256(lg, sm);
        float e = fast_exp2((lg - m) * 1.4426950408889634f);
        float se = brsum256(e, sm);
        conf_out[(size_t)q * C_NUM + c] = e / se;
    }
}

// ---------------- host ----------------------------------------------------------
extern "C" void kernel_launch(void* const* d_in, const int* in_sizes, int n_in,
                              void* d_out, int out_size) {
    (void)n_in; (void)in_sizes;
    const float* sup    = (const float*)d_in[0];
    const int*   labels = (const int*)d_in[1];
    const float* qry    = (const float*)d_in[2];
    const float* ls     = (const float*)d_in[3];
    const float* cp     = (const float*)d_in[4];

    float* out = (float*)d_out;
    const long long QC = (long long)Q_SZ * C_NUM;
    float* logits_out = out;
    float* uniq_out = nullptr;
    float* conf_out = nullptr;
    if ((long long)out_size >= 2 * QC + C_NUM) {
        uniq_out = out + QC;
        conf_out = out + QC + C_NUM;
    } else if ((long long)out_size >= QC + C_NUM) {
        uniq_out = out + QC;
    }

    cudaFuncSetAttribute(k_attn, cudaFuncAttributeMaxDynamicSharedMemorySize, SMEM_BYTES);

    k_init<<<512, 256>>>();                                        // 0
    k_norm_sup<<<S_SZ / NROWS_PB, 256>>>(sup, labels);             // 1
    k_mu_scan<<<1, 1024>>>();                                      // 2
    k_scatter<<<S_SZ / 256, 256>>>(labels);                        // 3
    k_centerquery<<<S_SZ + Q_SZ, 256>>>(qry);                      // 4
    k_attn<<<NWORKERS, 256, SMEM_BYTES>>>(ls);                     // 5
    k_final<<<Q_SZ, 256>>>(cp, logits_out, uniq_out, conf_out);    // 6
}

// round 14
// speedup vs baseline: 1.0675x; 1.0675x over previous
#include <cuda_runtime.h>
#include <cuda_bf16.h>
#include <math.h>
#include <stdint.h>

// Problem shape (fixed)
#define D_DIM 1024
#define C_NUM 256
#define S_SZ  16384
#define Q_SZ  4096

// HMMA tile config — single bf16 pass
#define BM 128
#define BN 128
#define BK 32
#define NKITER (D_DIM / BK)        // 32
#define NSTAGE 4
#define APITCH 80                  // padded row pitch bytes (64B data), conflict-free ldmatrix
#define MAT_BYTES (128 * APITCH)   // 10240
#define STAGE_BYTES (2 * MAT_BYTES)// A,B = 20480
#define SIMS_PITCH 132             // floats; multiple of 4 -> float4 aligned
#define SMEM_BYTES (NSTAGE * STAGE_BYTES)   // 81920 (sims 128*132*4=67584 overlays)

// persistent scheduling: unit = one (qtile, stile)
#define NQT (Q_SZ / BM)            // 32
#define NST (S_SZ / BN)            // 128
#define NUNITS (NQT * NST)         // 4096
#define NWORKERS 296               // 2 per SM

#define NROWS_PB 16                // rows per block in k_norm_sup

// ---------------- device scratch ----------------------------------------------
__device__ __align__(256) __nv_bfloat16 g_supNB[(size_t)S_SZ * D_DIM]; // l2-normalized (orig order)
__device__ __align__(256) __nv_bfloat16 g_supB[(size_t)S_SZ * D_DIM];  // centered, sorted
__device__ __align__(256) __nv_bfloat16 g_qryB[(size_t)Q_SZ * D_DIM];
__device__ float g_colsum8[8 * D_DIM];
__device__ int   g_counts[C_NUM];
__device__ float g_mu[D_DIM];
__device__ int   g_offsets[C_NUM];
__device__ int   g_cursor[C_NUM];
__device__ float g_logcounts[C_NUM];
__device__ int   g_slab[S_SZ];
__device__ int   g_srcidx[S_SZ];
__device__ float g_bins[(size_t)Q_SZ * C_NUM];
__device__ unsigned g_tilectr;

// ---------------- asm helpers ---------------------------------------------------
__device__ __forceinline__ uint32_t smem_u32(const void* p) {
    uint32_t a;
    asm("{ .reg .u64 t; cvta.to.shared.u64 t, %1; cvt.u32.u64 %0, t; }" : "=r"(a) : "l"(p));
    return a;
}
#define CP16(sa, g) \
    asm volatile("cp.async.cg.shared.global [%0], [%1], 16;" :: "r"(sa), "l"(g))
#define CP_COMMIT() asm volatile("cp.async.commit_group;" ::: "memory")
#define CP_WAIT2()  asm volatile("cp.async.wait_group 2;" ::: "memory")
#define CP_WAIT0()  asm volatile("cp.async.wait_group 0;" ::: "memory")
#define LDSM_X4(r0, r1, r2, r3, addr) \
    asm volatile("ldmatrix.sync.aligned.m8n8.x4.shared.b16 {%0,%1,%2,%3}, [%4];" \
                 : "=r"(r0), "=r"(r1), "=r"(r2), "=r"(r3) : "r"(addr))
#define MMA16816(d, a, b) \
    asm volatile("mma.sync.aligned.m16n8k16.row.col.f32.bf16.bf16.f32 " \
                 "{%0,%1,%2,%3}, {%4,%5,%6,%7}, {%8,%9}, {%0,%1,%2,%3};" \
                 : "+f"((d)[0]), "+f"((d)[1]), "+f"((d)[2]), "+f"((d)[3]) \
                 : "r"((a)[0]), "r"((a)[1]), "r"((a)[2]), "r"((a)[3]), \
                   "r"((b)[0]), "r"((b)[1]))

// 2^t via degree-6 poly on [-0.5,0.5] + exponent splice. rel err ~1e-8.
__device__ __forceinline__ float fast_exp2(float tt) {
    float n = rintf(tt);
    float f = tt - n;
    float p = 1.5403530394e-4f;
    p = fmaf(p, f, 1.3333558146e-3f);
    p = fmaf(p, f, 9.6181291076e-3f);
    p = fmaf(p, f, 5.5504108664e-2f);
    p = fmaf(p, f, 2.4022650696e-1f);
    p = fmaf(p, f, 6.9314718056e-1f);
    p = fmaf(p, f, 1.0f);
    int ni = (int)n;
    return p * __int_as_float((ni + 127) << 23);
}

// log2 via exponent split + atanh-form poly. abs err ~2e-5 over [1,2).
__device__ __forceinline__ float fast_log2(float x) {
    int bits = __float_as_int(x);
    int e = ((bits >> 23) & 255) - 127;
    float m = __int_as_float((bits & 0x007FFFFF) | 0x3F800000);  // [1,2)
    float tq = (m - 1.0f) / (m + 1.0f);
    float t2 = tq * tq;
    float p = 0.4121985831f;            // 2/(7 ln2)
    p = fmaf(p, t2, 0.5770780163f);     // 2/(5 ln2)
    p = fmaf(p, t2, 0.9617966939f);     // 2/(3 ln2)
    p = fmaf(p, t2, 2.8853900818f);     // 2/ln2
    return (float)e + p * tq;
}

// ---------------- block reductions (256 threads) -------------------------------
__device__ __forceinline__ float brsum256(float v, float* sm) {
#pragma unroll
    for (int o = 16; o > 0; o >>= 1) v += __shfl_xor_sync(0xffffffffu, v, o);
    __syncthreads();
    if ((threadIdx.x & 31) == 0) sm[threadIdx.x >> 5] = v;
    __syncthreads();
    float s = sm[0];
#pragma unroll
    for (int i = 1; i < 8; i++) s += sm[i];
    return s;
}
__device__ __forceinline__ float brmax256(float v, float* sm) {
#pragma unroll
    for (int o = 16; o > 0; o >>= 1) v = fmaxf(v, __shfl_xor_sync(0xffffffffu, v, o));
    __syncthreads();
    if ((threadIdx.x & 31) == 0) sm[threadIdx.x >> 5] = v;
    __syncthreads();
    float s = sm[0];
#pragma unroll
    for (int i = 1; i < 8; i++) s = fmaxf(s, sm[i]);
    return s;
}

__device__ __forceinline__ void bf16_store(__nv_bfloat16* dst, size_t row, int t, float4 v) {
    __nv_bfloat162 p0(__float2bfloat16(v.x), __float2bfloat16(v.y));
    __nv_bfloat162 p1(__float2bfloat16(v.z), __float2bfloat16(v.w));
    uint2 pv;
    pv.x = *(uint32_t*)&p0; pv.y = *(uint32_t*)&p1;
    ((uint2*)(dst + row * D_DIM))[t] = pv;
}
__device__ __forceinline__ float4 bf16_load4(const __nv_bfloat16* src, size_t row, int t) {
    uint2 pv = ((const uint2*)(src + row * D_DIM))[t];
    __nv_bfloat162 p0 = *(__nv_bfloat162*)&pv.x;
    __nv_bfloat162 p1 = *(__nv_bfloat162*)&pv.y;
    float4 v;
    v.x = __bfloat162float(p0.x); v.y = __bfloat162float(p0.y);
    v.z = __bfloat162float(p1.x); v.w = __bfloat162float(p1.y);
    return v;
}

// ---------------- prep kernels --------------------------------------------------
__global__ void k_init() {
    int i = blockIdx.x * blockDim.x + threadIdx.x;
    int stride = gridDim.x * blockDim.x;
    for (int j = i; j < Q_SZ * C_NUM; j += stride) g_bins[j] = 0.f;
    if (i < 8 * D_DIM) g_colsum8[i] = 0.f;
    if (i < C_NUM) { g_counts[i] = 0; g_cursor[i] = 0; }
    if (i == 0) g_tilectr = 0u;
}

// l2-normalize 16 rows/block (store bf16) + block-local colsum + label histogram,
// then one flush: 1024 colsum atomics + <=256 count atomics per block.
__global__ void k_norm_sup(const float* __restrict__ sup, const int* __restrict__ labels) {
    __shared__ float sm[8];
    __shared__ float cs[D_DIM];
    __shared__ int hist[C_NUM];
    int t = threadIdx.x;
#pragma unroll
    for (int j = 0; j < 4; j++) cs[t + j * 256] = 0.f;
    hist[t] = 0;
    __syncthreads();

    int r0 = blockIdx.x * NROWS_PB;
    for (int i = 0; i < NROWS_PB; i++) {
        int r = r0 + i;
        float4 v = ((const float4*)(sup + (size_t)r * D_DIM))[t];
        float ss = v.x * v.x + v.y * v.y + v.z * v.z + v.w * v.w;
        ss = brsum256(ss, sm);
        float inv = 1.f / fmaxf(sqrtf(ss), 1e-8f);
        v.x *= inv; v.y *= inv; v.z *= inv; v.w *= inv;
        bf16_store(g_supNB, (size_t)r, t, v);
        // thread t owns columns 4t..4t+3 -> no race
        cs[t * 4 + 0] += v.x;
        cs[t * 4 + 1] += v.y;
        cs[t * 4 + 2] += v.z;
        cs[t * 4 + 3] += v.w;
        if (t == 0) atomicAdd(&hist[labels[r]], 1);
    }
    __syncthreads();
    float* g = g_colsum8 + (blockIdx.x & 7) * D_DIM;
#pragma unroll
    for (int j = 0; j < 4; j++) atomicAdd(&g[t + j * 256], cs[t + j * 256]);
    if (hist[t]) atomicAdd(&g_counts[t], hist[t]);
}

// mu + parallel exclusive scan + logcounts (single block, 1024 threads)
__global__ void k_mu_scan() {
    __shared__ int sc_sm[C_NUM];
    int t = threadIdx.x;
    if (t < D_DIM) {
        float s = 0.f;
#pragma unroll
        for (int r = 0; r < 8; r++) s += g_colsum8[r * D_DIM + t];
        g_mu[t] = s / (float)S_SZ;
    }
    int cnt = 0;
    if (t < C_NUM) { cnt = g_counts[t]; sc_sm[t] = cnt; }
    __syncthreads();
#pragma unroll
    for (int off = 1; off < C_NUM; off <<= 1) {
        int v = 0;
        if (t < C_NUM && t >= off) v = sc_sm[t - off];
        __syncthreads();
        if (t < C_NUM) sc_sm[t] += v;
        __syncthreads();
    }
    if (t < C_NUM) {
        g_offsets[t] = sc_sm[t] - cnt;   // exclusive
        g_logcounts[t] = logf(fmaxf((float)cnt, 1.f));
    }
}

__global__ void k_scatter(const int* __restrict__ labels) {
    int s = blockIdx.x * blockDim.x + threadIdx.x;
    if (s < S_SZ) {
        int lb = labels[s];
        int pos = g_offsets[lb] + atomicAdd(&g_cursor[lb], 1);
        g_srcidx[pos] = s;
        g_slab[pos] = lb;
    }
}

// fused center(support, sorted order) + query transform — one row per block
// (per-row blocks hide the reduce/rsqrt latency chain best; R11 chunking regressed)
__global__ void k_centerquery(const float* __restrict__ qry) {
    __shared__ float sm[8];
    int b = blockIdx.x, t = threadIdx.x;
    if (b < S_SZ) {
        int src = g_srcidx[b];
        float4 v = bf16_load4(g_supNB, (size_t)src, t);
        float4 m = ((const float4*)g_mu)[t];
        v.x -= m.x; v.y -= m.y; v.z -= m.z; v.w -= m.w;
        float ss = v.x * v.x + v.y * v.y + v.z * v.z + v.w * v.w;
        ss = brsum256(ss, sm);
        float inv = 1.f / fmaxf(sqrtf(ss), 1e-8f);
        v.x *= inv; v.y *= inv; v.z *= inv; v.w *= inv;
        bf16_store(g_supB, (size_t)b, t, v);
    } else {
        int r = b - S_SZ;
        float4 v = ((const float4*)(qry + (size_t)r * D_DIM))[t];
        float ss = v.x * v.x + v.y * v.y + v.z * v.z + v.w * v.w;
        ss = brsum256(ss, sm);
        float inv = 1.f / fmaxf(sqrtf(ss), 1e-8f);
        v.x *= inv; v.y *= inv; v.z *= inv; v.w *= inv;
        float4 m = ((const float4*)g_mu)[t];
        v.x -= m.x; v.y -= m.y; v.z -= m.z; v.w -= m.w;
        float ss2 = v.x * v.x + v.y * v.y + v.z * v.z + v.w * v.w;
        ss2 = brsum256(ss2, sm);
        float inv2 = 1.f / fmaxf(sqrtf(ss2), 1e-8f);
        v.x *= inv2; v.y *= inv2; v.z *= inv2; v.w *= inv2;
        bf16_store(g_qryB, (size_t)r, t, v);
    }
}

// ---------------- fused persistent HMMA GEMM + exp + segment binning -----------
// Pipeline: 4 stages, single-kt commit groups, wait_group 2, issue kt+3 while
// reading kt (stage (kt+3)%4 never aliases stage kt%4 — proven R5/R7/R9-R12).
__global__ __launch_bounds__(256, 2)
void k_attn(const float* __restrict__ ls_ptr) {
    extern __shared__ __align__(16) char dsm[];
    __shared__ int slab_sm[128];
    __shared__ unsigned unit_sm;
    uint32_t smem_base = smem_u32(dsm);
    float* sims = (float*)dsm;   // overlay on stage buffers during epilogue

    int t = threadIdx.x;
    int wid = t >> 5, lane = t & 31;
    int wm = wid & 1, wn = wid >> 1;

    float sc = fminf(fmaxf(*ls_ptr, 1.f), 20.f);
    float scl2 = sc * 1.4426950408889634f;  // fold scale into log2(e)

    if (t == 0) unit_sm = atomicAdd(&g_tilectr, 1u);
    __syncthreads();
    unsigned u = unit_sm;

    while (u < NUNITS) {
        int q0 = (int)(u >> 7) * BM;
        int s0 = (int)(u & 127) * BN;
        if (t < BN) slab_sm[t] = g_slab[s0 + t];

        float acc[4][4][4];
#pragma unroll
        for (int mt = 0; mt < 4; mt++)
#pragma unroll
            for (int nt = 0; nt < 4; nt++)
#pragma unroll
                for (int e = 0; e < 4; e++) acc[mt][nt][e] = 0.f;

#define ISSUE(KT)                                                               \
        do {                                                                    \
            int kt_ = (KT);                                                     \
            if (kt_ < NKITER) {                                                 \
                int k0_ = kt_ * BK;                                             \
                uint32_t sb_ = smem_base + (kt_ % NSTAGE) * STAGE_BYTES;        \
                _Pragma("unroll")                                               \
                for (int m_ = 0; m_ < 2; m_++) {                                \
                    const __nv_bfloat16* base_ = (m_ == 0) ? g_qryB : g_supB;   \
                    int rb_ = (m_ == 0) ? q0 : s0;                              \
                    _Pragma("unroll")                                           \
                    for (int rc_ = 0; rc_ < 2; rc_++) {                         \
                        int i_ = t + rc_ * 256;                                 \
                        int row_ = i_ >> 2, ch_ = i_ & 3;                       \
                        const void* g_ = base_ +                                \
                            (size_t)(rb_ + row_) * D_DIM + k0_ + ch_ * 8;       \
                        uint32_t sa_ = sb_ + m_ * MAT_BYTES +                   \
                            row_ * APITCH + ch_ * 16;                           \
                        CP16(sa_, g_);                                          \
                    }                                                           \
                }                                                               \
            }                                                                   \
            CP_COMMIT();                                                        \
        } while (0)

        ISSUE(0);
        ISSUE(1);
        ISSUE(2);

        for (int kt = 0; kt < NKITER; kt++) {
            CP_WAIT2();
            __syncthreads();
            ISSUE(kt + 3);

            uint32_t sb = smem_base + (kt % NSTAGE) * STAGE_BYTES;
#pragma unroll
            for (int ks = 0; ks < 2; ks++) {
                uint32_t koff = ks * 32 + ((lane >> 4) << 4);
                uint32_t ah[4][4], bh[4][2];
#pragma unroll
                for (int mt = 0; mt < 4; mt++) {
                    uint32_t ra = sb + (uint32_t)(wm * 64 + mt * 16 + (lane & 15)) * APITCH + koff;
                    LDSM_X4(ah[mt][0], ah[mt][1], ah[mt][2], ah[mt][3], ra);
                }
#pragma unroll
                for (int p = 0; p < 2; p++) {
                    uint32_t rb2 = sb + MAT_BYTES +
                        (uint32_t)(wn * 32 + p * 16 + (lane & 15)) * APITCH + koff;
                    uint32_t x0, x1, x2, x3;
                    LDSM_X4(x0, x1, x2, x3, rb2);
                    bh[2 * p][0] = x0; bh[2 * p + 1][0] = x1;
                    bh[2 * p][1] = x2; bh[2 * p + 1][1] = x3;
                }
#pragma unroll
                for (int mt = 0; mt < 4; mt++)
#pragma unroll
                    for (int nt = 0; nt < 4; nt++)
                        MMA16816(acc[mt][nt], ah[mt], bh[nt]);
            }
        }
#undef ISSUE

        // ---- epilogue: prefetch next unit, exp -> sims smem -> binning ----
        CP_WAIT0();
        if (t == 0) unit_sm = atomicAdd(&g_tilectr, 1u);   // hide atomic latency
        __syncthreads();   // stages free; overlay sims

#pragma unroll
        for (int mt = 0; mt < 4; mt++) {
            int q = wm * 64 + mt * 16 + (lane >> 2);
#pragma unroll
            for (int nt = 0; nt < 4; nt++) {
                int c = wn * 32 + nt * 8 + (lane & 3) * 2;
                float2 v0, v1;
                v0.x = fast_exp2(acc[mt][nt][0] * scl2);
                v0.y = fast_exp2(acc[mt][nt][1] * scl2);
                v1.x = fast_exp2(acc[mt][nt][2] * scl2);
                v1.y = fast_exp2(acc[mt][nt][3] * scl2);
                *(float2*)&sims[(size_t)q * SIMS_PITCH + c] = v0;
                *(float2*)&sims[(size_t)(q + 8) * SIMS_PITCH + c] = v1;
            }
        }
        __syncthreads();

        {
            int q = t >> 1, h = t & 1;
            int cb = h * 64;
            const float* srow = &sims[(size_t)q * SIMS_PITCH + cb];
            float run = 0.f;
            int cur = slab_sm[cb];
#pragma unroll
            for (int i4 = 0; i4 < 16; i4++) {
                float4 v4 = *(const float4*)(srow + i4 * 4);
#pragma unroll
                for (int j = 0; j < 4; j++) {
                    int i = i4 * 4 + j;
                    int lb = slab_sm[cb + i];
                    float v = (j == 0) ? v4.x : (j == 1) ? v4.y : (j == 2) ? v4.z : v4.w;
                    if (lb != cur) {
                        atomicAdd(&g_bins[(size_t)(q0 + q) * C_NUM + cur], run);
                        run = 0.f; cur = lb;
                    }
                    run += v;
                }
            }
            atomicAdd(&g_bins[(size_t)(q0 + q) * C_NUM + cur], run);
        }
        __syncthreads();   // sims/slab reads done before next tile reuses smem
        u = unit_sm;
    }
}

// ---------------- finalize (uniq folded in: block 0 writes unique_classes) ------
__global__ void k_final(const float* __restrict__ cp_ptr,
                        float* __restrict__ logits_out,
                        float* __restrict__ uniq_out,
                        float* __restrict__ conf_out) {
    __shared__ float sm[8];
    const float LN2 = 0.6931471805599453f;
    int q = blockIdx.x, c = threadIdx.x;
    if (q == 0 && uniq_out) uniq_out[c] = (float)c;
    float mass = g_bins[(size_t)q * C_NUM + c];
    float Z = brsum256(mass, sm);
    float ratio = fmaxf(mass / Z, 1e-8f);
    float lg = fast_log2(ratio) * LN2 + (*cp_ptr) * g_logcounts[c];
    logits_out[(size_t)q * C_NUM + c] = lg;
    if (conf_out) {
        float m = brmax256(lg, sm);
        float e = fast_exp2((lg - m) * 1.4426950408889634f);
        float se = brsum256(e, sm);
        conf_out[(size_t)q * C_NUM + c] = e / se;
    }
}

// ---------------- host ----------------------------------------------------------
extern "C" void kernel_launch(void* const* d_in, const int* in_sizes, int n_in,
                              void* d_out, int out_size) {
    (void)n_in; (void)in_sizes;
    const float* sup    = (const float*)d_in[0];
    const int*   labels = (const int*)d_in[1];
    const float* qry    = (const float*)d_in[2];
    const float* ls     = (const float*)d_in[3];
    const float* cp     = (const float*)d_in[4];

    float* out = (float*)d_out;
    const long long QC = (long long)Q_SZ * C_NUM;
    float* logits_out = out;
    float* uniq_out = nullptr;
    float* conf_out = nullptr;
    if ((long long)out_size >= 2 * QC + C_NUM) {
        uniq_out = out + QC;
        conf_out = out + QC + C_NUM;
    } else if ((long long)out_size >= QC + C_NUM) {
        uniq_out = out + QC;
    }

    cudaFuncSetAttribute(k_attn, cudaFuncAttributeMaxDynamicSharedMemorySize, SMEM_BYTES);

    k_init<<<512, 256>>>();                                        // 0
    k_norm_sup<<<S_SZ / NROWS_PB, 256>>>(sup, labels);             // 1
    k_mu_scan<<<1, 1024>>>();                                      // 2
    k_scatter<<<S_SZ / 256, 256>>>(labels);                        // 3
    k_centerquery<<<S_SZ + Q_SZ, 256>>>(qry);                      // 4
    k_attn<<<NWORKERS, 256, SMEM_BYTES>>>(ls);                     // 5
    k_final<<<Q_SZ, 256>>>(cp, logits_out, uniq_out, conf_out);    // 6
}

// round 15
// speedup vs baseline: 1.0708x; 1.0031x over previous
#include <cuda_runtime.h>
#include <cuda_bf16.h>
#include <math.h>
#include <stdint.h>

// Problem shape (fixed)
#define D_DIM 1024
#define C_NUM 256
#define S_SZ  16384
#define Q_SZ  4096

// HMMA tile config — single bf16 pass
#define BM 128
#define BN 128
#define BK 32
#define NKITER (D_DIM / BK)        // 32
#define NSTAGE 4
#define APITCH 80                  // padded row pitch bytes (64B data), conflict-free ldmatrix
#define MAT_BYTES (128 * APITCH)   // 10240
#define STAGE_BYTES (2 * MAT_BYTES)// A,B = 20480
#define SIMS_PITCH 132             // floats; multiple of 4 -> float4 aligned
#define SMEM_BYTES (NSTAGE * STAGE_BYTES)   // 81920 (sims 128*132*4=67584 overlays)

// persistent scheduling: unit = one (qtile, stile)
#define NQT (Q_SZ / BM)            // 32
#define NST (S_SZ / BN)            // 128
#define NUNITS (NQT * NST)         // 4096
#define NWORKERS 296               // 2 per SM

#define NROWS_PB 16                // rows per block in k_norm_sup

// ---------------- device scratch ----------------------------------------------
__device__ __align__(256) __nv_bfloat16 g_supNB[(size_t)S_SZ * D_DIM]; // l2-normalized (orig order)
__device__ __align__(256) __nv_bfloat16 g_supB[(size_t)S_SZ * D_DIM];  // centered, sorted
__device__ __align__(256) __nv_bfloat16 g_qryB[(size_t)Q_SZ * D_DIM];
__device__ float g_colsum8[8 * D_DIM];
__device__ int   g_counts[C_NUM];
__device__ float g_mu[D_DIM];
__device__ int   g_offsets[C_NUM];
__device__ int   g_cursor[C_NUM];
__device__ float g_logcounts[C_NUM];
__device__ int   g_slab[S_SZ];
__device__ int   g_srcidx[S_SZ];
__device__ float g_bins[(size_t)Q_SZ * C_NUM];
__device__ unsigned g_tilectr;

// ---------------- asm helpers ---------------------------------------------------
__device__ __forceinline__ uint32_t smem_u32(const void* p) {
    uint32_t a;
    asm("{ .reg .u64 t; cvta.to.shared.u64 t, %1; cvt.u32.u64 %0, t; }" : "=r"(a) : "l"(p));
    return a;
}
#define CP16(sa, g) \
    asm volatile("cp.async.cg.shared.global [%0], [%1], 16;" :: "r"(sa), "l"(g))
#define CP_COMMIT() asm volatile("cp.async.commit_group;" ::: "memory")
#define CP_WAIT2()  asm volatile("cp.async.wait_group 2;" ::: "memory")
#define CP_WAIT0()  asm volatile("cp.async.wait_group 0;" ::: "memory")
#define LDSM_X4(r0, r1, r2, r3, addr) \
    asm volatile("ldmatrix.sync.aligned.m8n8.x4.shared.b16 {%0,%1,%2,%3}, [%4];" \
                 : "=r"(r0), "=r"(r1), "=r"(r2), "=r"(r3) : "r"(addr))
#define MMA16816(d, a, b) \
    asm volatile("mma.sync.aligned.m16n8k16.row.col.f32.bf16.bf16.f32 " \
                 "{%0,%1,%2,%3}, {%4,%5,%6,%7}, {%8,%9}, {%0,%1,%2,%3};" \
                 : "+f"((d)[0]), "+f"((d)[1]), "+f"((d)[2]), "+f"((d)[3]) \
                 : "r"((a)[0]), "r"((a)[1]), "r"((a)[2]), "r"((a)[3]), \
                   "r"((b)[0]), "r"((b)[1]))

// 2^t via degree-6 poly on [-0.5,0.5] + exponent splice. rel err ~1e-8.
__device__ __forceinline__ float fast_exp2(float tt) {
    float n = rintf(tt);
    float f = tt - n;
    float p = 1.5403530394e-4f;
    p = fmaf(p, f, 1.3333558146e-3f);
    p = fmaf(p, f, 9.6181291076e-3f);
    p = fmaf(p, f, 5.5504108664e-2f);
    p = fmaf(p, f, 2.4022650696e-1f);
    p = fmaf(p, f, 6.9314718056e-1f);
    p = fmaf(p, f, 1.0f);
    int ni = (int)n;
    return p * __int_as_float((ni + 127) << 23);
}

// log2 via exponent split + atanh-form poly. abs err ~2e-5 over [1,2).
__device__ __forceinline__ float fast_log2(float x) {
    int bits = __float_as_int(x);
    int e = ((bits >> 23) & 255) - 127;
    float m = __int_as_float((bits & 0x007FFFFF) | 0x3F800000);  // [1,2)
    float tq = (m - 1.0f) / (m + 1.0f);
    float t2 = tq * tq;
    float p = 0.4121985831f;            // 2/(7 ln2)
    p = fmaf(p, t2, 0.5770780163f);     // 2/(5 ln2)
    p = fmaf(p, t2, 0.9617966939f);     // 2/(3 ln2)
    p = fmaf(p, t2, 2.8853900818f);     // 2/ln2
    return (float)e + p * tq;
}

// ---------------- block reductions (256 threads) -------------------------------
__device__ __forceinline__ float brsum256(float v, float* sm) {
#pragma unroll
    for (int o = 16; o > 0; o >>= 1) v += __shfl_xor_sync(0xffffffffu, v, o);
    __syncthreads();
    if ((threadIdx.x & 31) == 0) sm[threadIdx.x >> 5] = v;
    __syncthreads();
    float s = sm[0];
#pragma unroll
    for (int i = 1; i < 8; i++) s += sm[i];
    return s;
}

__device__ __forceinline__ void bf16_store(__nv_bfloat16* dst, size_t row, int t, float4 v) {
    __nv_bfloat162 p0(__float2bfloat16(v.x), __float2bfloat16(v.y));
    __nv_bfloat162 p1(__float2bfloat16(v.z), __float2bfloat16(v.w));
    uint2 pv;
    pv.x = *(uint32_t*)&p0; pv.y = *(uint32_t*)&p1;
    ((uint2*)(dst + row * D_DIM))[t] = pv;
}
__device__ __forceinline__ float4 bf16_load4(const __nv_bfloat16* src, size_t row, int t) {
    uint2 pv = ((const uint2*)(src + row * D_DIM))[t];
    __nv_bfloat162 p0 = *(__nv_bfloat162*)&pv.x;
    __nv_bfloat162 p1 = *(__nv_bfloat162*)&pv.y;
    float4 v;
    v.x = __bfloat162float(p0.x); v.y = __bfloat162float(p0.y);
    v.z = __bfloat162float(p1.x); v.w = __bfloat162float(p1.y);
    return v;
}

// ---------------- prep kernels --------------------------------------------------
__global__ void k_init() {
    int i = blockIdx.x * blockDim.x + threadIdx.x;
    int stride = gridDim.x * blockDim.x;
    for (int j = i; j < Q_SZ * C_NUM; j += stride) g_bins[j] = 0.f;
    if (i < 8 * D_DIM) g_colsum8[i] = 0.f;
    if (i < C_NUM) { g_counts[i] = 0; g_cursor[i] = 0; }
    if (i == 0) g_tilectr = 0u;
}

// l2-normalize 16 rows/block (store bf16) + block-local colsum + label histogram,
// then one flush: 1024 colsum atomics + <=256 count atomics per block.
__global__ void k_norm_sup(const float* __restrict__ sup, const int* __restrict__ labels) {
    __shared__ float sm[8];
    __shared__ float cs[D_DIM];
    __shared__ int hist[C_NUM];
    int t = threadIdx.x;
#pragma unroll
    for (int j = 0; j < 4; j++) cs[t + j * 256] = 0.f;
    hist[t] = 0;
    __syncthreads();

    int r0 = blockIdx.x * NROWS_PB;
    for (int i = 0; i < NROWS_PB; i++) {
        int r = r0 + i;
        float4 v = ((const float4*)(sup + (size_t)r * D_DIM))[t];
        float ss = v.x * v.x + v.y * v.y + v.z * v.z + v.w * v.w;
        ss = brsum256(ss, sm);
        float inv = 1.f / fmaxf(sqrtf(ss), 1e-8f);
        v.x *= inv; v.y *= inv; v.z *= inv; v.w *= inv;
        bf16_store(g_supNB, (size_t)r, t, v);
        // thread t owns columns 4t..4t+3 -> no race
        cs[t * 4 + 0] += v.x;
        cs[t * 4 + 1] += v.y;
        cs[t * 4 + 2] += v.z;
        cs[t * 4 + 3] += v.w;
        if (t == 0) atomicAdd(&hist[labels[r]], 1);
    }
    __syncthreads();
    float* g = g_colsum8 + (blockIdx.x & 7) * D_DIM;
#pragma unroll
    for (int j = 0; j < 4; j++) atomicAdd(&g[t + j * 256], cs[t + j * 256]);
    if (hist[t]) atomicAdd(&g_counts[t], hist[t]);
}

// mu + parallel exclusive scan + logcounts (single block, 1024 threads)
__global__ void k_mu_scan() {
    __shared__ int sc_sm[C_NUM];
    int t = threadIdx.x;
    if (t < D_DIM) {
        float s = 0.f;
#pragma unroll
        for (int r = 0; r < 8; r++) s += g_colsum8[r * D_DIM + t];
        g_mu[t] = s / (float)S_SZ;
    }
    int cnt = 0;
    if (t < C_NUM) { cnt = g_counts[t]; sc_sm[t] = cnt; }
    __syncthreads();
#pragma unroll
    for (int off = 1; off < C_NUM; off <<= 1) {
        int v = 0;
        if (t < C_NUM && t >= off) v = sc_sm[t - off];
        __syncthreads();
        if (t < C_NUM) sc_sm[t] += v;
        __syncthreads();
    }
    if (t < C_NUM) {
        g_offsets[t] = sc_sm[t] - cnt;   // exclusive
        g_logcounts[t] = logf(fmaxf((float)cnt, 1.f));
    }
}

__global__ void k_scatter(const int* __restrict__ labels) {
    int s = blockIdx.x * blockDim.x + threadIdx.x;
    if (s < S_SZ) {
        int lb = labels[s];
        int pos = g_offsets[lb] + atomicAdd(&g_cursor[lb], 1);
        g_srcidx[pos] = s;
        g_slab[pos] = lb;
    }
}

// fused center(support, sorted order) + query transform — one row per block
// (per-row blocks hide the reduce/rsqrt latency chain best; R11 chunking regressed)
__global__ void k_centerquery(const float* __restrict__ qry) {
    __shared__ float sm[8];
    int b = blockIdx.x, t = threadIdx.x;
    if (b < S_SZ) {
        int src = g_srcidx[b];
        float4 v = bf16_load4(g_supNB, (size_t)src, t);
        float4 m = ((const float4*)g_mu)[t];
        v.x -= m.x; v.y -= m.y; v.z -= m.z; v.w -= m.w;
        float ss = v.x * v.x + v.y * v.y + v.z * v.z + v.w * v.w;
        ss = brsum256(ss, sm);
        float inv = 1.f / fmaxf(sqrtf(ss), 1e-8f);
        v.x *= inv; v.y *= inv; v.z *= inv; v.w *= inv;
        bf16_store(g_supB, (size_t)b, t, v);
    } else {
        int r = b - S_SZ;
        float4 v = ((const float4*)(qry + (size_t)r * D_DIM))[t];
        float ss = v.x * v.x + v.y * v.y + v.z * v.z + v.w * v.w;
        ss = brsum256(ss, sm);
        float inv = 1.f / fmaxf(sqrtf(ss), 1e-8f);
        v.x *= inv; v.y *= inv; v.z *= inv; v.w *= inv;
        float4 m = ((const float4*)g_mu)[t];
        v.x -= m.x; v.y -= m.y; v.z -= m.z; v.w -= m.w;
        float ss2 = v.x * v.x + v.y * v.y + v.z * v.z + v.w * v.w;
        ss2 = brsum256(ss2, sm);
        float inv2 = 1.f / fmaxf(sqrtf(ss2), 1e-8f);
        v.x *= inv2; v.y *= inv2; v.z *= inv2; v.w *= inv2;
        bf16_store(g_qryB, (size_t)r, t, v);
    }
}

// ---------------- fused persistent HMMA GEMM + exp + segment binning -----------
// Pipeline: 4 stages, single-kt commit groups, wait_group 2, issue kt+3 while
// reading kt (stage (kt+3)%4 never aliases stage kt%4 — proven R5/R7/R9-R14).
__global__ __launch_bounds__(256, 2)
void k_attn(const float* __restrict__ ls_ptr) {
    extern __shared__ __align__(16) char dsm[];
    __shared__ int slab_sm[128];
    __shared__ unsigned unit_sm;
    uint32_t smem_base = smem_u32(dsm);
    float* sims = (float*)dsm;   // overlay on stage buffers during epilogue

    int t = threadIdx.x;
    int wid = t >> 5, lane = t & 31;
    int wm = wid & 1, wn = wid >> 1;

    float sc = fminf(fmaxf(*ls_ptr, 1.f), 20.f);
    float scl2 = sc * 1.4426950408889634f;  // fold scale into log2(e)

    if (t == 0) unit_sm = atomicAdd(&g_tilectr, 1u);
    __syncthreads();
    unsigned u = unit_sm;

    while (u < NUNITS) {
        int q0 = (int)(u >> 7) * BM;
        int s0 = (int)(u & 127) * BN;
        if (t < BN) slab_sm[t] = g_slab[s0 + t];

        float acc[4][4][4];
#pragma unroll
        for (int mt = 0; mt < 4; mt++)
#pragma unroll
            for (int nt = 0; nt < 4; nt++)
#pragma unroll
                for (int e = 0; e < 4; e++) acc[mt][nt][e] = 0.f;

#define ISSUE(KT)                                                               \
        do {                                                                    \
            int kt_ = (KT);                                                     \
            if (kt_ < NKITER) {                                                 \
                int k0_ = kt_ * BK;                                             \
                uint32_t sb_ = smem_base + (kt_ % NSTAGE) * STAGE_BYTES;        \
                _Pragma("unroll")                                               \
                for (int m_ = 0; m_ < 2; m_++) {                                \
                    const __nv_bfloat16* base_ = (m_ == 0) ? g_qryB : g_supB;   \
                    int rb_ = (m_ == 0) ? q0 : s0;                              \
                    _Pragma("unroll")                                           \
                    for (int rc_ = 0; rc_ < 2; rc_++) {                         \
                        int i_ = t + rc_ * 256;                                 \
                        int row_ = i_ >> 2, ch_ = i_ & 3;                       \
                        const void* g_ = base_ +                                \
                            (size_t)(rb_ + row_) * D_DIM + k0_ + ch_ * 8;       \
                        uint32_t sa_ = sb_ + m_ * MAT_BYTES +                   \
                            row_ * APITCH + ch_ * 16;                           \
                        CP16(sa_, g_);                                          \
                    }                                                           \
                }                                                               \
            }                                                                   \
            CP_COMMIT();                                                        \
        } while (0)

        ISSUE(0);
        ISSUE(1);
        ISSUE(2);

        for (int kt = 0; kt < NKITER; kt++) {
            CP_WAIT2();
            __syncthreads();
            ISSUE(kt + 3);

            uint32_t sb = smem_base + (kt % NSTAGE) * STAGE_BYTES;
#pragma unroll
            for (int ks = 0; ks < 2; ks++) {
                uint32_t koff = ks * 32 + ((lane >> 4) << 4);
                uint32_t ah[4][4], bh[4][2];
#pragma unroll
                for (int mt = 0; mt < 4; mt++) {
                    uint32_t ra = sb + (uint32_t)(wm * 64 + mt * 16 + (lane & 15)) * APITCH + koff;
                    LDSM_X4(ah[mt][0], ah[mt][1], ah[mt][2], ah[mt][3], ra);
                }
#pragma unroll
                for (int p = 0; p < 2; p++) {
                    uint32_t rb2 = sb + MAT_BYTES +
                        (uint32_t)(wn * 32 + p * 16 + (lane & 15)) * APITCH + koff;
                    uint32_t x0, x1, x2, x3;
                    LDSM_X4(x0, x1, x2, x3, rb2);
                    bh[2 * p][0] = x0; bh[2 * p + 1][0] = x1;
                    bh[2 * p][1] = x2; bh[2 * p + 1][1] = x3;
                }
#pragma unroll
                for (int mt = 0; mt < 4; mt++)
#pragma unroll
                    for (int nt = 0; nt < 4; nt++)
                        MMA16816(acc[mt][nt], ah[mt], bh[nt]);
            }
        }
#undef ISSUE

        // ---- epilogue: prefetch next unit, exp -> sims smem -> binning ----
        CP_WAIT0();
        if (t == 0) unit_sm = atomicAdd(&g_tilectr, 1u);   // hide atomic latency
        __syncthreads();   // stages free; overlay sims

#pragma unroll
        for (int mt = 0; mt < 4; mt++) {
            int q = wm * 64 + mt * 16 + (lane >> 2);
#pragma unroll
            for (int nt = 0; nt < 4; nt++) {
                int c = wn * 32 + nt * 8 + (lane & 3) * 2;
                float2 v0, v1;
                v0.x = fast_exp2(acc[mt][nt][0] * scl2);
                v0.y = fast_exp2(acc[mt][nt][1] * scl2);
                v1.x = fast_exp2(acc[mt][nt][2] * scl2);
                v1.y = fast_exp2(acc[mt][nt][3] * scl2);
                *(float2*)&sims[(size_t)q * SIMS_PITCH + c] = v0;
                *(float2*)&sims[(size_t)(q + 8) * SIMS_PITCH + c] = v1;
            }
        }
        __syncthreads();

        {
            int q = t >> 1, h = t & 1;
            int cb = h * 64;
            const float* srow = &sims[(size_t)q * SIMS_PITCH + cb];
            float run = 0.f;
            int cur = slab_sm[cb];
#pragma unroll
            for (int i4 = 0; i4 < 16; i4++) {
                float4 v4 = *(const float4*)(srow + i4 * 4);
#pragma unroll
                for (int j = 0; j < 4; j++) {
                    int i = i4 * 4 + j;
                    int lb = slab_sm[cb + i];
                    float v = (j == 0) ? v4.x : (j == 1) ? v4.y : (j == 2) ? v4.z : v4.w;
                    if (lb != cur) {
                        atomicAdd(&g_bins[(size_t)(q0 + q) * C_NUM + cur], run);
                        run = 0.f; cur = lb;
                    }
                    run += v;
                }
            }
            atomicAdd(&g_bins[(size_t)(q0 + q) * C_NUM + cur], run);
        }
        __syncthreads();   // sims/slab reads done before next tile reuses smem
        u = unit_sm;
    }
}

// ---------------- finalize: warp per query, shuffle-only reductions -------------
// 8 warps/block, warp w -> query blockIdx.x*8+w; lane owns 8 contiguous classes
// (two float4 loads, coalesced). Zero __syncthreads, zero smem.
__global__ __launch_bounds__(256)
void k_final(const float* __restrict__ cp_ptr,
             float* __restrict__ logits_out,
             float* __restrict__ uniq_out,
             float* __restrict__ conf_out) {
    const float LN2 = 0.6931471805599453f;
    const float INV_LN2 = 1.4426950408889634f;
    int t = threadIdx.x;
    int w = t >> 5, lane = t & 31;
    int q = blockIdx.x * 8 + w;
    if (blockIdx.x == 0 && uniq_out && t < C_NUM) uniq_out[t] = (float)t;

    const float* brow = g_bins + (size_t)q * C_NUM + lane * 8;
    float4 m0 = ((const float4*)brow)[0];
    float4 m1 = ((const float4*)brow)[1];
    float v[8] = { m0.x, m0.y, m0.z, m0.w, m1.x, m1.y, m1.z, m1.w };

    float z = 0.f;
#pragma unroll
    for (int j = 0; j < 8; j++) z += v[j];
#pragma unroll
    for (int o = 16; o > 0; o >>= 1) z += __shfl_xor_sync(0xffffffffu, z, o);

    float cp = *cp_ptr;
    float lg[8], mx = -1e30f;
#pragma unroll
    for (int j = 0; j < 8; j++) {
        float ratio = fmaxf(v[j] / z, 1e-8f);
        lg[j] = fast_log2(ratio) * LN2 + cp * g_logcounts[lane * 8 + j];
        mx = fmaxf(mx, lg[j]);
    }
    float4 o0 = { lg[0], lg[1], lg[2], lg[3] };
    float4 o1 = { lg[4], lg[5], lg[6], lg[7] };
    float* lrow = logits_out + (size_t)q * C_NUM + lane * 8;
    ((float4*)lrow)[0] = o0;
    ((float4*)lrow)[1] = o1;

    if (conf_out) {
#pragma unroll
        for (int o = 16; o > 0; o >>= 1) mx = fmaxf(mx, __shfl_xor_sync(0xffffffffu, mx, o));
        float e[8], se = 0.f;
#pragma unroll
        for (int j = 0; j < 8; j++) { e[j] = fast_exp2((lg[j] - mx) * INV_LN2); se += e[j]; }
#pragma unroll
        for (int o = 16; o > 0; o >>= 1) se += __shfl_xor_sync(0xffffffffu, se, o);
        float inv = 1.f / se;
        float4 c0 = { e[0] * inv, e[1] * inv, e[2] * inv, e[3] * inv };
        float4 c1 = { e[4] * inv, e[5] * inv, e[6] * inv, e[7] * inv };
        float* crow = conf_out + (size_t)q * C_NUM + lane * 8;
        ((float4*)crow)[0] = c0;
        ((float4*)crow)[1] = c1;
    }
}

// ---------------- host ----------------------------------------------------------
extern "C" void kernel_launch(void* const* d_in, const int* in_sizes, int n_in,
                              void* d_out, int out_size) {
    (void)n_in; (void)in_sizes;
    const float* sup    = (const float*)d_in[0];
    const int*   labels = (const int*)d_in[1];
    const float* qry    = (const float*)d_in[2];
    const float* ls     = (const float*)d_in[3];
    const float* cp     = (const float*)d_in[4];

    float* out = (float*)d_out;
    const long long QC = (long long)Q_SZ * C_NUM;
    float* logits_out = out;
    float* uniq_out = nullptr;
    float* conf_out = nullptr;
    if ((long long)out_size >= 2 * QC + C_NUM) {
        uniq_out = out + QC;
        conf_out = out + QC + C_NUM;
    } else if ((long long)out_size >= QC + C_NUM) {
        uniq_out = out + QC;
    }

    cudaFuncSetAttribute(k_attn, cudaFuncAttributeMaxDynamicSharedMemorySize, SMEM_BYTES);

    k_init<<<512, 256>>>();                                        // 0
    k_norm_sup<<<S_SZ / NROWS_PB, 256>>>(sup, labels);             // 1
    k_mu_scan<<<1, 1024>>>();                                      // 2
    k_scatter<<<S_SZ / 256, 256>>>(labels);                        // 3
    k_centerquery<<<S_SZ + Q_SZ, 256>>>(qry);                      // 4
    k_attn<<<NWORKERS, 256, SMEM_BYTES>>>(ls);                     // 5
    k_final<<<Q_SZ / 8, 256>>>(cp, logits_out, uniq_out, conf_out);// 6
}

// round 16
// speedup vs baseline: 1.0728x; 1.0018x over previous
#include <cuda_runtime.h>
#include <cuda_bf16.h>
#include <math.h>
#include <stdint.h>

// Problem shape (fixed)
#define D_DIM 1024
#define C_NUM 256
#define S_SZ  16384
#define Q_SZ  4096

// HMMA tile config — single bf16 pass
#define BM 128
#define BN 128
#define BK 32
#define NKITER (D_DIM / BK)        // 32
#define NSTAGE 4
#define APITCH 80                  // padded row pitch bytes (64B data), conflict-free ldmatrix
#define MAT_BYTES (128 * APITCH)   // 10240
#define STAGE_BYTES (2 * MAT_BYTES)// A,B = 20480
#define SIMS_PITCH 132             // floats; multiple of 4 -> float4 aligned
#define SMEM_BYTES (NSTAGE * STAGE_BYTES)   // 81920 (sims 128*132*4=67584 overlays)

// persistent scheduling: unit = one (qtile, stile)
#define NQT (Q_SZ / BM)            // 32
#define NST (S_SZ / BN)            // 128
#define NUNITS (NQT * NST)         // 4096
#define NWORKERS 296               // 2 per SM

#define NROWS_PB 16                // rows per block in k_norm_sup

// ---------------- device scratch ----------------------------------------------
__device__ __align__(256) __nv_bfloat16 g_supNB[(size_t)S_SZ * D_DIM]; // l2-normalized (orig order)
__device__ __align__(256) __nv_bfloat16 g_supB[(size_t)S_SZ * D_DIM];  // centered, sorted
__device__ __align__(256) __nv_bfloat16 g_qryB[(size_t)Q_SZ * D_DIM];
__device__ float g_colsum8[8 * D_DIM];
__device__ int   g_counts[C_NUM];
__device__ float g_mu[D_DIM];
__device__ int   g_offsets[C_NUM];
__device__ int   g_cursor[C_NUM];
__device__ float g_logcounts[C_NUM];
__device__ int   g_slab[S_SZ];
__device__ int   g_srcidx[S_SZ];
__device__ __align__(16) float g_bins[(size_t)Q_SZ * C_NUM];
__device__ unsigned g_tilectr;

// ---------------- asm helpers ---------------------------------------------------
__device__ __forceinline__ uint32_t smem_u32(const void* p) {
    uint32_t a;
    asm("{ .reg .u64 t; cvta.to.shared.u64 t, %1; cvt.u32.u64 %0, t; }" : "=r"(a) : "l"(p));
    return a;
}
#define CP16(sa, g) \
    asm volatile("cp.async.cg.shared.global [%0], [%1], 16;" :: "r"(sa), "l"(g))
#define CP_COMMIT() asm volatile("cp.async.commit_group;" ::: "memory")
#define CP_WAIT2()  asm volatile("cp.async.wait_group 2;" ::: "memory")
#define CP_WAIT0()  asm volatile("cp.async.wait_group 0;" ::: "memory")
#define LDSM_X4(r0, r1, r2, r3, addr) \
    asm volatile("ldmatrix.sync.aligned.m8n8.x4.shared.b16 {%0,%1,%2,%3}, [%4];" \
                 : "=r"(r0), "=r"(r1), "=r"(r2), "=r"(r3) : "r"(addr))
#define MMA16816(d, a, b) \
    asm volatile("mma.sync.aligned.m16n8k16.row.col.f32.bf16.bf16.f32 " \
                 "{%0,%1,%2,%3}, {%4,%5,%6,%7}, {%8,%9}, {%0,%1,%2,%3};" \
                 : "+f"((d)[0]), "+f"((d)[1]), "+f"((d)[2]), "+f"((d)[3]) \
                 : "r"((a)[0]), "r"((a)[1]), "r"((a)[2]), "r"((a)[3]), \
                   "r"((b)[0]), "r"((b)[1]))

// 2^t via degree-6 poly on [-0.5,0.5] + exponent splice. rel err ~1e-8.
__device__ __forceinline__ float fast_exp2(float tt) {
    float n = rintf(tt);
    float f = tt - n;
    float p = 1.5403530394e-4f;
    p = fmaf(p, f, 1.3333558146e-3f);
    p = fmaf(p, f, 9.6181291076e-3f);
    p = fmaf(p, f, 5.5504108664e-2f);
    p = fmaf(p, f, 2.4022650696e-1f);
    p = fmaf(p, f, 6.9314718056e-1f);
    p = fmaf(p, f, 1.0f);
    int ni = (int)n;
    return p * __int_as_float((ni + 127) << 23);
}

// log2 via exponent split + atanh-form poly. abs err ~2e-5 over [1,2).
__device__ __forceinline__ float fast_log2(float x) {
    int bits = __float_as_int(x);
    int e = ((bits >> 23) & 255) - 127;
    float m = __int_as_float((bits & 0x007FFFFF) | 0x3F800000);  // [1,2)
    float tq = (m - 1.0f) / (m + 1.0f);
    float t2 = tq * tq;
    float p = 0.4121985831f;            // 2/(7 ln2)
    p = fmaf(p, t2, 0.5770780163f);     // 2/(5 ln2)
    p = fmaf(p, t2, 0.9617966939f);     // 2/(3 ln2)
    p = fmaf(p, t2, 2.8853900818f);     // 2/ln2
    return (float)e + p * tq;
}

// ---------------- block reductions (256 threads) -------------------------------
__device__ __forceinline__ float brsum256(float v, float* sm) {
#pragma unroll
    for (int o = 16; o > 0; o >>= 1) v += __shfl_xor_sync(0xffffffffu, v, o);
    __syncthreads();
    if ((threadIdx.x & 31) == 0) sm[threadIdx.x >> 5] = v;
    __syncthreads();
    float s = sm[0];
#pragma unroll
    for (int i = 1; i < 8; i++) s += sm[i];
    return s;
}

__device__ __forceinline__ void bf16_store(__nv_bfloat16* dst, size_t row, int t, float4 v) {
    __nv_bfloat162 p0(__float2bfloat16(v.x), __float2bfloat16(v.y));
    __nv_bfloat162 p1(__float2bfloat16(v.z), __float2bfloat16(v.w));
    uint2 pv;
    pv.x = *(uint32_t*)&p0; pv.y = *(uint32_t*)&p1;
    ((uint2*)(dst + row * D_DIM))[t] = pv;
}
__device__ __forceinline__ float4 bf16_load4(const __nv_bfloat16* src, size_t row, int t) {
    uint2 pv = ((const uint2*)(src + row * D_DIM))[t];
    __nv_bfloat162 p0 = *(__nv_bfloat162*)&pv.x;
    __nv_bfloat162 p1 = *(__nv_bfloat162*)&pv.y;
    float4 v;
    v.x = __bfloat162float(p0.x); v.y = __bfloat162float(p0.y);
    v.z = __bfloat162float(p1.x); v.w = __bfloat162float(p1.y);
    return v;
}

// ---------------- prep kernels --------------------------------------------------
__global__ void k_init() {
    int i = blockIdx.x * blockDim.x + threadIdx.x;
    int stride = gridDim.x * blockDim.x;
    const float4 z4 = { 0.f, 0.f, 0.f, 0.f };
    float4* b4 = (float4*)g_bins;
    for (int j = i; j < (Q_SZ * C_NUM) / 4; j += stride) b4[j] = z4;
    if (i < 8 * D_DIM) g_colsum8[i] = 0.f;
    if (i < C_NUM) { g_counts[i] = 0; g_cursor[i] = 0; }
    if (i == 0) g_tilectr = 0u;
}

// l2-normalize 16 rows/block (store bf16) + block-local colsum + label histogram,
// then one flush: 1024 colsum atomics + <=256 count atomics per block.
__global__ void k_norm_sup(const float* __restrict__ sup, const int* __restrict__ labels) {
    __shared__ float sm[8];
    __shared__ float cs[D_DIM];
    __shared__ int hist[C_NUM];
    int t = threadIdx.x;
#pragma unroll
    for (int j = 0; j < 4; j++) cs[t + j * 256] = 0.f;
    hist[t] = 0;
    __syncthreads();

    int r0 = blockIdx.x * NROWS_PB;
    for (int i = 0; i < NROWS_PB; i++) {
        int r = r0 + i;
        float4 v = ((const float4*)(sup + (size_t)r * D_DIM))[t];
        float ss = v.x * v.x + v.y * v.y + v.z * v.z + v.w * v.w;
        ss = brsum256(ss, sm);
        float inv = 1.f / fmaxf(sqrtf(ss), 1e-8f);
        v.x *= inv; v.y *= inv; v.z *= inv; v.w *= inv;
        bf16_store(g_supNB, (size_t)r, t, v);
        // thread t owns columns 4t..4t+3 -> no race
        cs[t * 4 + 0] += v.x;
        cs[t * 4 + 1] += v.y;
        cs[t * 4 + 2] += v.z;
        cs[t * 4 + 3] += v.w;
        if (t == 0) atomicAdd(&hist[labels[r]], 1);
    }
    __syncthreads();
    float* g = g_colsum8 + (blockIdx.x & 7) * D_DIM;
#pragma unroll
    for (int j = 0; j < 4; j++) atomicAdd(&g[t + j * 256], cs[t + j * 256]);
    if (hist[t]) atomicAdd(&g_counts[t], hist[t]);
}

// mu + parallel exclusive scan + logcounts (single block, 1024 threads)
__global__ void k_mu_scan() {
    __shared__ int sc_sm[C_NUM];
    int t = threadIdx.x;
    if (t < D_DIM) {
        float s = 0.f;
#pragma unroll
        for (int r = 0; r < 8; r++) s += g_colsum8[r * D_DIM + t];
        g_mu[t] = s / (float)S_SZ;
    }
    int cnt = 0;
    if (t < C_NUM) { cnt = g_counts[t]; sc_sm[t] = cnt; }
    __syncthreads();
#pragma unroll
    for (int off = 1; off < C_NUM; off <<= 1) {
        int v = 0;
        if (t < C_NUM && t >= off) v = sc_sm[t - off];
        __syncthreads();
        if (t < C_NUM) sc_sm[t] += v;
        __syncthreads();
    }
    if (t < C_NUM) {
        g_offsets[t] = sc_sm[t] - cnt;   // exclusive
        g_logcounts[t] = logf(fmaxf((float)cnt, 1.f));
    }
}

__global__ void k_scatter(const int* __restrict__ labels) {
    int s = blockIdx.x * blockDim.x + threadIdx.x;
    if (s < S_SZ) {
        int lb = labels[s];
        int pos = g_offsets[lb] + atomicAdd(&g_cursor[lb], 1);
        g_srcidx[pos] = s;
        g_slab[pos] = lb;
    }
}

// fused center(support, sorted order) + query transform — one row per block
// (per-row blocks hide the reduce/rsqrt latency chain best; R11 chunking regressed)
__global__ void k_centerquery(const float* __restrict__ qry) {
    __shared__ float sm[8];
    int b = blockIdx.x, t = threadIdx.x;
    if (b < S_SZ) {
        int src = g_srcidx[b];
        float4 v = bf16_load4(g_supNB, (size_t)src, t);
        float4 m = ((const float4*)g_mu)[t];
        v.x -= m.x; v.y -= m.y; v.z -= m.z; v.w -= m.w;
        float ss = v.x * v.x + v.y * v.y + v.z * v.z + v.w * v.w;
        ss = brsum256(ss, sm);
        float inv = 1.f / fmaxf(sqrtf(ss), 1e-8f);
        v.x *= inv; v.y *= inv; v.z *= inv; v.w *= inv;
        bf16_store(g_supB, (size_t)b, t, v);
    } else {
        int r = b - S_SZ;
        float4 v = ((const float4*)(qry + (size_t)r * D_DIM))[t];
        float ss = v.x * v.x + v.y * v.y + v.z * v.z + v.w * v.w;
        ss = brsum256(ss, sm);
        float inv = 1.f / fmaxf(sqrtf(ss), 1e-8f);
        v.x *= inv; v.y *= inv; v.z *= inv; v.w *= inv;
        float4 m = ((const float4*)g_mu)[t];
        v.x -= m.x; v.y -= m.y; v.z -= m.z; v.w -= m.w;
        float ss2 = v.x * v.x + v.y * v.y + v.z * v.z + v.w * v.w;
        ss2 = brsum256(ss2, sm);
        float inv2 = 1.f / fmaxf(sqrtf(ss2), 1e-8f);
        v.x *= inv2; v.y *= inv2; v.z *= inv2; v.w *= inv2;
        bf16_store(g_qryB, (size_t)r, t, v);
    }
}

// ---------------- fused persistent HMMA GEMM + exp + segment binning -----------
// Pipeline: 4 stages, single-kt commit groups, wait_group 2, issue kt+3 while
// reading kt (stage (kt+3)%4 never aliases stage kt%4 — proven R5/R7/R9-R15).
__global__ __launch_bounds__(256, 2)
void k_attn(const float* __restrict__ ls_ptr) {
    extern __shared__ __align__(16) char dsm[];
    __shared__ int slab_sm[128];
    __shared__ unsigned unit_sm;
    uint32_t smem_base = smem_u32(dsm);
    float* sims = (float*)dsm;   // overlay on stage buffers during epilogue

    int t = threadIdx.x;
    int wid = t >> 5, lane = t & 31;
    int wm = wid & 1, wn = wid >> 1;

    float sc = fminf(fmaxf(*ls_ptr, 1.f), 20.f);
    float scl2 = sc * 1.4426950408889634f;  // fold scale into log2(e)

    if (t == 0) unit_sm = atomicAdd(&g_tilectr, 1u);
    __syncthreads();
    unsigned u = unit_sm;

    while (u < NUNITS) {
        int q0 = (int)(u >> 7) * BM;
        int s0 = (int)(u & 127) * BN;
        if (t < BN) slab_sm[t] = g_slab[s0 + t];

        float acc[4][4][4];
#pragma unroll
        for (int mt = 0; mt < 4; mt++)
#pragma unroll
            for (int nt = 0; nt < 4; nt++)
#pragma unroll
                for (int e = 0; e < 4; e++) acc[mt][nt][e] = 0.f;

#define ISSUE(KT)                                                               \
        do {                                                                    \
            int kt_ = (KT);                                                     \
            if (kt_ < NKITER) {                                                 \
                int k0_ = kt_ * BK;                                             \
                uint32_t sb_ = smem_base + (kt_ % NSTAGE) * STAGE_BYTES;        \
                _Pragma("unroll")                                               \
                for (int m_ = 0; m_ < 2; m_++) {                                \
                    const __nv_bfloat16* base_ = (m_ == 0) ? g_qryB : g_supB;   \
                    int rb_ = (m_ == 0) ? q0 : s0;                              \
                    _Pragma("unroll")                                           \
                    for (int rc_ = 0; rc_ < 2; rc_++) {                         \
                        int i_ = t + rc_ * 256;                                 \
                        int row_ = i_ >> 2, ch_ = i_ & 3;                       \
                        const void* g_ = base_ +                                \
                            (size_t)(rb_ + row_) * D_DIM + k0_ + ch_ * 8;       \
                        uint32_t sa_ = sb_ + m_ * MAT_BYTES +                   \
                            row_ * APITCH + ch_ * 16;                           \
                        CP16(sa_, g_);                                          \
                    }                                                           \
                }                                                               \
            }                                                                   \
            CP_COMMIT();                                                        \
        } while (0)

        ISSUE(0);
        ISSUE(1);
        ISSUE(2);

        for (int kt = 0; kt < NKITER; kt++) {
            CP_WAIT2();
            __syncthreads();
            ISSUE(kt + 3);

            uint32_t sb = smem_base + (kt % NSTAGE) * STAGE_BYTES;
#pragma unroll
            for (int ks = 0; ks < 2; ks++) {
                uint32_t koff = ks * 32 + ((lane >> 4) << 4);
                uint32_t ah[4][4], bh[4][2];
#pragma unroll
                for (int mt = 0; mt < 4; mt++) {
                    uint32_t ra = sb + (uint32_t)(wm * 64 + mt * 16 + (lane & 15)) * APITCH + koff;
                    LDSM_X4(ah[mt][0], ah[mt][1], ah[mt][2], ah[mt][3], ra);
                }
#pragma unroll
                for (int p = 0; p < 2; p++) {
                    uint32_t rb2 = sb + MAT_BYTES +
                        (uint32_t)(wn * 32 + p * 16 + (lane & 15)) * APITCH + koff;
                    uint32_t x0, x1, x2, x3;
                    LDSM_X4(x0, x1, x2, x3, rb2);
                    bh[2 * p][0] = x0; bh[2 * p + 1][0] = x1;
                    bh[2 * p][1] = x2; bh[2 * p + 1][1] = x3;
                }
#pragma unroll
                for (int mt = 0; mt < 4; mt++)
#pragma unroll
                    for (int nt = 0; nt < 4; nt++)
                        MMA16816(acc[mt][nt], ah[mt], bh[nt]);
            }
        }
#undef ISSUE

        // ---- epilogue: prefetch next unit, exp -> sims smem -> binning ----
        CP_WAIT0();
        if (t == 0) unit_sm = atomicAdd(&g_tilectr, 1u);   // hide atomic latency
        __syncthreads();   // stages free; overlay sims

#pragma unroll
        for (int mt = 0; mt < 4; mt++) {
            int q = wm * 64 + mt * 16 + (lane >> 2);
#pragma unroll
            for (int nt = 0; nt < 4; nt++) {
                int c = wn * 32 + nt * 8 + (lane & 3) * 2;
                float2 v0, v1;
                v0.x = fast_exp2(acc[mt][nt][0] * scl2);
                v0.y = fast_exp2(acc[mt][nt][1] * scl2);
                v1.x = fast_exp2(acc[mt][nt][2] * scl2);
                v1.y = fast_exp2(acc[mt][nt][3] * scl2);
                *(float2*)&sims[(size_t)q * SIMS_PITCH + c] = v0;
                *(float2*)&sims[(size_t)(q + 8) * SIMS_PITCH + c] = v1;
            }
        }
        __syncthreads();

        {
            int q = t >> 1, h = t & 1;
            int cb = h * 64;
            const float* srow = &sims[(size_t)q * SIMS_PITCH + cb];
            float run = 0.f;
            int cur = slab_sm[cb];
#pragma unroll
            for (int i4 = 0; i4 < 16; i4++) {
                float4 v4 = *(const float4*)(srow + i4 * 4);
#pragma unroll
                for (int j = 0; j < 4; j++) {
                    int i = i4 * 4 + j;
                    int lb = slab_sm[cb + i];
                    float v = (j == 0) ? v4.x : (j == 1) ? v4.y : (j == 2) ? v4.z : v4.w;
                    if (lb != cur) {
                        atomicAdd(&g_bins[(size_t)(q0 + q) * C_NUM + cur], run);
                        run = 0.f; cur = lb;
                    }
                    run += v;
                }
            }
            atomicAdd(&g_bins[(size_t)(q0 + q) * C_NUM + cur], run);
        }
        __syncthreads();   // sims/slab reads done before next tile reuses smem
        u = unit_sm;
    }
}

// ---------------- finalize: warp per query, shuffle-only reductions -------------
// 8 warps/block, warp w -> query blockIdx.x*8+w; lane owns 8 contiguous classes
// (two float4 loads, coalesced). Zero __syncthreads, zero smem.
__global__ __launch_bounds__(256)
void k_final(const float* __restrict__ cp_ptr,
             float* __restrict__ logits_out,
             float* __restrict__ uniq_out,
             float* __restrict__ conf_out) {
    const float LN2 = 0.6931471805599453f;
    const float INV_LN2 = 1.4426950408889634f;
    int t = threadIdx.x;
    int w = t >> 5, lane = t & 31;
    int q = blockIdx.x * 8 + w;
    if (blockIdx.x == 0 && uniq_out && t < C_NUM) uniq_out[t] = (float)t;

    const float* brow = g_bins + (size_t)q * C_NUM + lane * 8;
    float4 m0 = ((const float4*)brow)[0];
    float4 m1 = ((const float4*)brow)[1];
    float v[8] = { m0.x, m0.y, m0.z, m0.w, m1.x, m1.y, m1.z, m1.w };

    float z = 0.f;
#pragma unroll
    for (int j = 0; j < 8; j++) z += v[j];
#pragma unroll
    for (int o = 16; o > 0; o >>= 1) z += __shfl_xor_sync(0xffffffffu, z, o);

    float cp = *cp_ptr;
    float lg[8], mx = -1e30f;
#pragma unroll
    for (int j = 0; j < 8; j++) {
        float ratio = fmaxf(v[j] / z, 1e-8f);
        lg[j] = fast_log2(ratio) * LN2 + cp * g_logcounts[lane * 8 + j];
        mx = fmaxf(mx, lg[j]);
    }
    float4 o0 = { lg[0], lg[1], lg[2], lg[3] };
    float4 o1 = { lg[4], lg[5], lg[6], lg[7] };
    float* lrow = logits_out + (size_t)q * C_NUM + lane * 8;
    ((float4*)lrow)[0] = o0;
    ((float4*)lrow)[1] = o1;

    if (conf_out) {
#pragma unroll
        for (int o = 16; o > 0; o >>= 1) mx = fmaxf(mx, __shfl_xor_sync(0xffffffffu, mx, o));
        float e[8], se = 0.f;
#pragma unroll
        for (int j = 0; j < 8; j++) { e[j] = fast_exp2((lg[j] - mx) * INV_LN2); se += e[j]; }
#pragma unroll
        for (int o = 16; o > 0; o >>= 1) se += __shfl_xor_sync(0xffffffffu, se, o);
        float inv = 1.f / se;
        float4 c0 = { e[0] * inv, e[1] * inv, e[2] * inv, e[3] * inv };
        float4 c1 = { e[4] * inv, e[5] * inv, e[6] * inv, e[7] * inv };
        float* crow = conf_out + (size_t)q * C_NUM + lane * 8;
        ((float4*)crow)[0] = c0;
        ((float4*)crow)[1] = c1;
    }
}

// ---------------- host ----------------------------------------------------------
extern "C" void kernel_launch(void* const* d_in, const int* in_sizes, int n_in,
                              void* d_out, int out_size) {
    (void)n_in; (void)in_sizes;
    const float* sup    = (const float*)d_in[0];
    const int*   labels = (const int*)d_in[1];
    const float* qry    = (const float*)d_in[2];
    const float* ls     = (const float*)d_in[3];
    const float* cp     = (const float*)d_in[4];

    float* out = (float*)d_out;
    const long long QC = (long long)Q_SZ * C_NUM;
    float* logits_out = out;
    float* uniq_out = nullptr;
    float* conf_out = nullptr;
    if ((long long)out_size >= 2 * QC + C_NUM) {
        uniq_out = out + QC;
        conf_out = out + QC + C_NUM;
    } else if ((long long)out_size >= QC + C_NUM) {
        uniq_out = out + QC;
    }

    cudaFuncSetAttribute(k_attn, cudaFuncAttributeMaxDynamicSharedMemorySize, SMEM_BYTES);

    k_init<<<512, 256>>>();                                        // 0
    k_norm_sup<<<S_SZ / NROWS_PB, 256>>>(sup, labels);             // 1
    k_mu_scan<<<1, 1024>>>();                                      // 2
    k_scatter<<<S_SZ / 256, 256>>>(labels);                        // 3
    k_centerquery<<<S_SZ + Q_SZ, 256>>>(qry);                      // 4
    k_attn<<<NWORKERS, 256, SMEM_BYTES>>>(ls);                     // 5
    k_final<<<Q_SZ / 8, 256>>>(cp, logits_out, uniq_out, conf_out);// 6
}